// round 5
// baseline (speedup 1.0000x reference)
#include <cuda_runtime.h>
#include <mma.h>
using namespace nvcuda;

#define BB  4
#define TT  2048
#define CC  1024
#define NH_ 16
#define HS_ 64
#define HB_ (BB * NH_)   // 64 (b,h) pairs

// Scratch (device globals — no allocation allowed)
__device__ float g_q[(size_t)BB * NH_ * TT * HS_];   // [B,NH,T,HS]
__device__ float g_k[(size_t)BB * NH_ * TT * HS_];
__device__ float g_v[(size_t)BB * NH_ * TT * HS_];
__device__ float g_y[(size_t)BB * TT * CC];          // [B,T,NH,HS] == [B,T,C]

__device__ __forceinline__ float ftf(float x) { return wmma::__float_to_tf32(x); }
__device__ __forceinline__ float ex2(float x) {
    float r; asm("ex2.approx.ftz.f32 %0, %1;" : "=f"(r) : "f"(x)); return r;
}
template<class Frag> __device__ __forceinline__ void cvt_frag(Frag& f) {
#pragma unroll
    for (int e = 0; e < f.num_elements; e++) f.x[e] = wmma::__float_to_tf32(f.x[e]);
}
__device__ __forceinline__ unsigned su32(const void* p) {
    return (unsigned)__cvta_generic_to_shared(p);
}
#define CPA16(dst, src) \
    asm volatile("cp.async.cg.shared.global [%0], [%1], 16;" :: "r"(dst), "l"(src))
#define CPCOMMIT() asm volatile("cp.async.commit_group;")
template<int N> __device__ __forceinline__ void cpwait() {
    asm volatile("cp.async.wait_group %0;" :: "n"(N));
}

// ---------------------------------------------------------------------------
// TF32 GEMM, cp.async 2-stage pipeline: C = A @ W^T.
// Block 128x128, BK=32, 256 threads = 8 warps (2m x 4n), warp tile 64x32.
// Raw fp32 in smem; TF32 cvt at fragment load. Dynamic smem 72KB.
// EPI==0: scatter into g_q/g_k/g_v; EPI==1: plain store, A read from g_y.
// ---------------------------------------------------------------------------
#define GLD 36
#define GTILE (128 * GLD)
#define GEMM_SMEM (4 * GTILE * 4)

template<int EPI>
__global__ __launch_bounds__(256, 2) void gemm_tf32_kernel(
    const float* __restrict__ A, const float* __restrict__ W,
    float* __restrict__ out)
{
    extern __shared__ float sh[];   // [A0 | A1 | B0 | B1], each 128x36

    const int tid = threadIdx.x;
    const int bn = blockIdx.x, bm = blockIdx.y;
    const int warp = tid >> 5;
    const int wm = warp >> 2, wn = warp & 3;
    const int lrow = tid >> 1, lcb = (tid & 1) * 16;

    const float* Asrc = (EPI == 1) ? (const float*)g_y : A;
    const float* Ag = Asrc + (size_t)(bm * 128 + lrow) * CC + lcb;
    const float* Wg = W + (size_t)(bn * 128 + lrow) * CC + lcb;

    wmma::fragment<wmma::accumulator, 16, 16, 8, float> cf[4][2];
#pragma unroll
    for (int i = 0; i < 4; i++)
#pragma unroll
        for (int j = 0; j < 2; j++) wmma::fill_fragment(cf[i][j], 0.0f);

    auto issue = [&](int it, int s) {
        unsigned da = su32(sh + s * GTILE + lrow * GLD + lcb);
        unsigned db = su32(sh + (2 + s) * GTILE + lrow * GLD + lcb);
        const float* ga = Ag + it * 32;
        const float* gb = Wg + it * 32;
#pragma unroll
        for (int u = 0; u < 4; u++) {
            CPA16(da + u * 16, ga + u * 4);
            CPA16(db + u * 16, gb + u * 4);
        }
        CPCOMMIT();
    };

    issue(0, 0);
    const int NIT = CC / 32;
    for (int it = 0; it < NIT; it++) {
        if (it + 1 < NIT) { issue(it + 1, (it + 1) & 1); cpwait<1>(); }
        else              { cpwait<0>(); }
        __syncthreads();
        const float* As = sh + (it & 1) * GTILE;
        const float* Bs = sh + (2 + (it & 1)) * GTILE;
#pragma unroll
        for (int ks = 0; ks < 4; ks++) {
            wmma::fragment<wmma::matrix_a, 16, 16, 8, wmma::precision::tf32, wmma::row_major> af[4];
            wmma::fragment<wmma::matrix_b, 16, 16, 8, wmma::precision::tf32, wmma::col_major> bf[2];
#pragma unroll
            for (int i = 0; i < 4; i++) {
                wmma::load_matrix_sync(af[i], &As[(wm * 64 + i * 16) * GLD + ks * 8], GLD);
                cvt_frag(af[i]);
            }
#pragma unroll
            for (int j = 0; j < 2; j++) {
                wmma::load_matrix_sync(bf[j], &Bs[(wn * 32 + j * 16) * GLD + ks * 8], GLD);
                cvt_frag(bf[j]);
            }
#pragma unroll
            for (int i = 0; i < 4; i++)
#pragma unroll
                for (int j = 0; j < 2; j++)
                    wmma::mma_sync(cf[i][j], af[i], bf[j], cf[i][j]);
        }
        __syncthreads();
    }

#pragma unroll
    for (int i = 0; i < 4; i++) {
        int m0 = bm * 128 + wm * 64 + i * 16;
#pragma unroll
        for (int j = 0; j < 2; j++) {
            int n = bn * 128 + wn * 32 + j * 16;
            if (EPI == 0) {
                int b_ = m0 >> 11;
                int t  = m0 & 2047;
                int which = n >> 10;
                int c = n & 1023;
                int head = c >> 6;
                int d = c & 63;
                float* dst = (which == 0) ? g_q : ((which == 1) ? g_k : g_v);
                wmma::store_matrix_sync(
                    &dst[(((size_t)(b_ * NH_ + head)) * TT + t) * HS_ + d],
                    cf[i][j], HS_, wmma::mem_row_major);
            } else {
                wmma::store_matrix_sync(&out[(size_t)m0 * CC + n],
                                        cf[i][j], CC, wmma::mem_row_major);
            }
        }
    }
}

// ---------------------------------------------------------------------------
// Flash attention, TF32, cp.async double-buffered K/V, Q tile 128.
// 256 threads = 8 warps; warp w owns rows [16w, 16w+16). Causal skipping:
// warp-level full-skip on the tail chunk + per-tile skip on diagonal chunks.
// smem: K0|K1|V0|V1 (64x68 each) | Ss (128x68) = 102KB dynamic.
// ---------------------------------------------------------------------------
#define FLD 68
#define FKV (64 * FLD)
#define FSS (128 * FLD)
#define FLASH_SMEM ((4 * FKV + FSS) * 4)

__global__ __launch_bounds__(256, 2) void flash_tf32_kernel()
{
    extern __shared__ float sh[];
    float* Ss = sh + 4 * FKV;

    const int qt = gridDim.x - 1 - blockIdx.x;   // heavy tiles first
    const int hb = blockIdx.y;
    const int tid = threadIdx.x;
    const int warp = tid >> 5;
    const int r = tid >> 1, h = tid & 1;         // softmax: row, col-half
    const int lr = tid >> 2, lq = (tid & 3) * 16; // K/V loader lane

    const int nc = 2 * qt + 2;

    auto issue = [&](int c, int s) {
        const float* kp = g_k + ((size_t)hb * TT + c * 64 + lr) * HS_ + lq;
        const float* vp = g_v + ((size_t)hb * TT + c * 64 + lr) * HS_ + lq;
        unsigned dk = su32(sh + s * FKV + lr * FLD + lq);
        unsigned dv = su32(sh + (2 + s) * FKV + lr * FLD + lq);
#pragma unroll
        for (int u = 0; u < 4; u++) {
            CPA16(dk + u * 16, kp + u * 4);
            CPA16(dv + u * 16, vp + u * 4);
        }
        CPCOMMIT();
    };

    issue(0, 0);

    // ---- stage Q (scaled by 1/8 * log2e, tf32) into own Ss band ----
    const float* qp = g_q + ((size_t)hb * TT + qt * 128) * HS_;
    const float qs = 0.125f * 1.44269504f;
#pragma unroll
    for (int u = 0; u < 8; u++) {
        float4 v = *(const float4*)(qp + r * 64 + h * 32 + u * 4);
        v.x = ftf(v.x * qs); v.y = ftf(v.y * qs);
        v.z = ftf(v.z * qs); v.w = ftf(v.w * qs);
        *(float4*)&Ss[r * FLD + h * 32 + u * 4] = v;
    }
    __syncwarp();
    wmma::fragment<wmma::matrix_a, 16, 16, 8, wmma::precision::tf32, wmma::row_major> qf[8];
#pragma unroll
    for (int ks = 0; ks < 8; ks++)
        wmma::load_matrix_sync(qf[ks], &Ss[(warp * 16) * FLD + ks * 8], FLD);
    __syncwarp();

    float m_r = -1e30f, l_r = 0.0f;
    float O[32];
#pragma unroll
    for (int j = 0; j < 32; j++) O[j] = 0.0f;

    for (int c = 0; c < nc; c++) {
        if (c + 1 < nc) { issue(c + 1, (c + 1) & 1); cpwait<1>(); }
        else            { cpwait<0>(); }
        __syncthreads();
        const float* Ks = sh + (c & 1) * FKV;
        const float* Vs = sh + (2 + (c & 1)) * FKV;

        // causal limit for this warp on this chunk (keys 64c.. vs rows 128qt+16w..)
        const int lim = (c >= 2 * qt) ? (16 * warp + 15 - 64 * (c - 2 * qt)) : 1023;
        if (lim >= 0) {
            const int jmax = min(3, lim >> 4);
            const int ksmax = min(7, lim >> 3);

            // ---- S = Q K^T ----
            wmma::fragment<wmma::accumulator, 16, 16, 8, float> sc[4];
#pragma unroll
            for (int j = 0; j < 4; j++) wmma::fill_fragment(sc[j], 0.0f);
#pragma unroll
            for (int ks = 0; ks < 8; ks++) {
#pragma unroll
                for (int j = 0; j < 4; j++) {
                    if (j > jmax) break;
                    wmma::fragment<wmma::matrix_b, 16, 16, 8, wmma::precision::tf32, wmma::col_major> kf;
                    wmma::load_matrix_sync(kf, &Ks[(j * 16) * FLD + ks * 8], FLD);
                    cvt_frag(kf);
                    wmma::mma_sync(sc[j], qf[ks], kf, sc[j]);
                }
            }
#pragma unroll
            for (int j = 0; j < 4; j++) {
                if (j > jmax) break;
                wmma::store_matrix_sync(&Ss[(warp * 16) * FLD + j * 16], sc[j],
                                        FLD, wmma::mem_row_major);
            }
            __syncwarp();

            // ---- online softmax (2 threads per row), base-2 domain ----
            float p[32];
#pragma unroll
            for (int u = 0; u < 8; u++) {
                float4 s4 = *(const float4*)&Ss[r * FLD + h * 32 + u * 4];
                p[u*4+0] = s4.x; p[u*4+1] = s4.y; p[u*4+2] = s4.z; p[u*4+3] = s4.w;
            }
            if (c >= 2 * qt) {
                const int koff = 64 * (c - 2 * qt) + h * 32;
#pragma unroll
                for (int j = 0; j < 32; j++)
                    if (koff + j > r) p[j] = -1e30f;
            }
            float rm = -1e30f;
#pragma unroll
            for (int j = 0; j < 32; j++) rm = fmaxf(rm, p[j]);
            rm = fmaxf(rm, __shfl_xor_sync(0xffffffffu, rm, 1));
            float mnew = fmaxf(m_r, rm);
            float corr = ex2(m_r - mnew);
            float rs = 0.0f;
#pragma unroll
            for (int j = 0; j < 32; j++) { p[j] = ex2(p[j] - mnew); rs += p[j]; }
            rs += __shfl_xor_sync(0xffffffffu, rs, 1);
            l_r = l_r * corr + rs;
            m_r = mnew;
#pragma unroll
            for (int j = 0; j < 32; j++) O[j] *= corr;
#pragma unroll
            for (int u = 0; u < 8; u++) {
                float4 p4 = make_float4(ftf(p[u*4+0]), ftf(p[u*4+1]),
                                        ftf(p[u*4+2]), ftf(p[u*4+3]));
                *(float4*)&Ss[r * FLD + h * 32 + u * 4] = p4;
            }
            __syncwarp();

            // ---- O += P @ V ----
            wmma::fragment<wmma::accumulator, 16, 16, 8, float> pv[4];
#pragma unroll
            for (int j = 0; j < 4; j++) wmma::fill_fragment(pv[j], 0.0f);
#pragma unroll
            for (int ks = 0; ks < 8; ks++) {
                if (ks > ksmax) break;
                wmma::fragment<wmma::matrix_a, 16, 16, 8, wmma::precision::tf32, wmma::row_major> pf;
                wmma::load_matrix_sync(pf, &Ss[(warp * 16) * FLD + ks * 8], FLD);
#pragma unroll
                for (int j = 0; j < 4; j++) {
                    wmma::fragment<wmma::matrix_b, 16, 16, 8, wmma::precision::tf32, wmma::row_major> vf;
                    wmma::load_matrix_sync(vf, &Vs[(ks * 8) * FLD + j * 16], FLD);
                    cvt_frag(vf);
                    wmma::mma_sync(pv[j], pf, vf, pv[j]);
                }
            }
#pragma unroll
            for (int j = 0; j < 4; j++)
                wmma::store_matrix_sync(&Ss[(warp * 16) * FLD + j * 16], pv[j],
                                        FLD, wmma::mem_row_major);
            __syncwarp();
#pragma unroll
            for (int u = 0; u < 8; u++) {
                float4 ov = *(const float4*)&Ss[r * FLD + h * 32 + u * 4];
                O[u*4+0] += ov.x; O[u*4+1] += ov.y;
                O[u*4+2] += ov.z; O[u*4+3] += ov.w;
            }
        }
        __syncthreads();   // all warps done with this stage before it's reissued
    }

    // ---- write O in [B,T,NH,HS] layout ----
    float inv = 1.0f / l_r;
    const int b_ = hb >> 4, head = hb & 15;
    const int t = qt * 128 + r;
    float* yp = g_y + (((size_t)(b_ * TT + t)) * NH_ + head) * HS_ + h * 32;
#pragma unroll
    for (int u = 0; u < 8; u++) {
        float4 val = make_float4(O[u*4+0]*inv, O[u*4+1]*inv,
                                 O[u*4+2]*inv, O[u*4+3]*inv);
        *(float4*)(yp + u * 4) = val;
    }
}

// ---------------------------------------------------------------------------
extern "C" void kernel_launch(void* const* d_in, const int* in_sizes, int n_in,
                              void* d_out, int out_size)
{
    const float* x      = (const float*)d_in[0];  // [B,T,C]
    const float* W_attn = (const float*)d_in[1];  // [3C,C]
    const float* W_proj = (const float*)d_in[2];  // [C,C]
    // d_in[3..6] feed a discarded branch — skipped.
    float* out = (float*)d_out;                   // [B,T,C] fp32

    cudaFuncSetAttribute(gemm_tf32_kernel<0>,
                         cudaFuncAttributeMaxDynamicSharedMemorySize, GEMM_SMEM);
    cudaFuncSetAttribute(gemm_tf32_kernel<1>,
                         cudaFuncAttributeMaxDynamicSharedMemorySize, GEMM_SMEM);
    cudaFuncSetAttribute(flash_tf32_kernel,
                         cudaFuncAttributeMaxDynamicSharedMemorySize, FLASH_SMEM);

    gemm_tf32_kernel<0><<<dim3(3 * CC / 128, BB * TT / 128), 256, GEMM_SMEM>>>(x, W_attn, nullptr);
    flash_tf32_kernel<<<dim3(TT / 128, HB_), 256, FLASH_SMEM>>>();
    gemm_tf32_kernel<1><<<dim3(CC / 128, BB * TT / 128), 256, GEMM_SMEM>>>(x, W_proj, out);
}

// round 7
// speedup vs baseline: 1.2197x; 1.2197x over previous
#include <cuda_runtime.h>
#include <mma.h>
#include <cstdint>
using namespace nvcuda;

#define BB  4
#define TT  2048
#define CC  1024
#define NH_ 16
#define HS_ 64
#define HB_ (BB * NH_)   // 64 (b,h) pairs

// Scratch (device globals — no allocation allowed)
__device__ float g_q[(size_t)BB * NH_ * TT * HS_];   // [B,NH,T,HS], tf32-rounded
__device__ float g_k[(size_t)BB * NH_ * TT * HS_];
__device__ float g_v[(size_t)BB * NH_ * TT * HS_];
__device__ float g_y[(size_t)BB * TT * CC];          // [B,T,NH,HS] == [B,T,C]

__device__ __forceinline__ float ftf(float x) { return wmma::__float_to_tf32(x); }
__device__ __forceinline__ float4 ftf4(float4 v) {
    return make_float4(ftf(v.x), ftf(v.y), ftf(v.z), ftf(v.w));
}
__device__ __forceinline__ float ex2(float x) {
    float r; asm("ex2.approx.ftz.f32 %0, %1;" : "=f"(r) : "f"(x)); return r;
}
__device__ __forceinline__ unsigned su32(const void* p) {
    return (unsigned)__cvta_generic_to_shared(p);
}
#define CPA16(dst, src) \
    asm volatile("cp.async.cg.shared.global [%0], [%1], 16;" :: "r"(dst), "l"(src))
#define CPCOMMIT() asm volatile("cp.async.commit_group;")
template<int N> __device__ __forceinline__ void cpwait() {
    asm volatile("cp.async.wait_group %0;" :: "n"(N));
}

// Raw tf32 MMA, documented register layout (lane l: g=l>>2, tg=l&3):
//   A (16x8): a0=(g,tg) a1=(g+8,tg) a2=(g,tg+4) a3=(g+8,tg+4)
//   B (8x8):  b0=(tg,g) b1=(tg+4,g)
//   C (16x8): c0=(g,2tg) c1=(g,2tg+1) c2=(g+8,2tg) c3=(g+8,2tg+1)
__device__ __forceinline__ void mma_tf32(float* d,
    uint32_t a0, uint32_t a1, uint32_t a2, uint32_t a3,
    uint32_t b0, uint32_t b1)
{
    asm volatile("mma.sync.aligned.m16n8k8.row.col.f32.tf32.tf32.f32 "
        "{%0,%1,%2,%3}, {%4,%5,%6,%7}, {%8,%9}, {%0,%1,%2,%3};"
        : "+f"(d[0]), "+f"(d[1]), "+f"(d[2]), "+f"(d[3])
        : "r"(a0), "r"(a1), "r"(a2), "r"(a3), "r"(b0), "r"(b1));
}

// ---------------------------------------------------------------------------
// TF32 GEMM (R4 structure — best measured): C = A @ W^T.
// Block 128x128, BK=32, 256 threads, 8 warps (2m x 4n), warp tile 64x32.
// tf32-converted at smem store; fragments load ready.
// EPI==0: scatter tf32-rounded q/k/v; EPI==1: plain fp32 store from g_y.
// ---------------------------------------------------------------------------
template<int EPI>
__global__ __launch_bounds__(256) void gemm_tf32_kernel(
    const float* __restrict__ A, const float* __restrict__ W,
    float* __restrict__ out)
{
    __shared__ float As[128][36];
    __shared__ float Bs[128][36];

    const int tid = threadIdx.x;
    const int bn = blockIdx.x, bm = blockIdx.y;
    const int warp = tid >> 5;
    const int wm = warp >> 2, wn = warp & 3;
    const int lrow = tid >> 1, lcol = (tid & 1) * 16;

    wmma::fragment<wmma::accumulator, 16, 16, 8, float> cf[4][2];
#pragma unroll
    for (int i = 0; i < 4; i++)
#pragma unroll
        for (int j = 0; j < 2; j++) wmma::fill_fragment(cf[i][j], 0.0f);

    const float* Asrc = (EPI == 1) ? (const float*)g_y : A;
    const float* Ab = Asrc + (size_t)(bm * 128 + lrow) * CC + lcol;
    const float* Wb = W + (size_t)(bn * 128 + lrow) * CC + lcol;

    for (int k0 = 0; k0 < CC; k0 += 32) {
        float4 a[4], b[4];
#pragma unroll
        for (int u = 0; u < 4; u++) {
            a[u] = *(const float4*)(Ab + k0 + u * 4);
            b[u] = *(const float4*)(Wb + k0 + u * 4);
        }
        __syncthreads();
#pragma unroll
        for (int u = 0; u < 4; u++) {
            *(float4*)&As[lrow][lcol + u * 4] = ftf4(a[u]);
            *(float4*)&Bs[lrow][lcol + u * 4] = ftf4(b[u]);
        }
        __syncthreads();
#pragma unroll
        for (int ks = 0; ks < 4; ks++) {
            wmma::fragment<wmma::matrix_a, 16, 16, 8, wmma::precision::tf32, wmma::row_major> af[4];
            wmma::fragment<wmma::matrix_b, 16, 16, 8, wmma::precision::tf32, wmma::col_major> bf[2];
#pragma unroll
            for (int i = 0; i < 4; i++)
                wmma::load_matrix_sync(af[i], &As[wm * 64 + i * 16][ks * 8], 36);
#pragma unroll
            for (int j = 0; j < 2; j++)
                wmma::load_matrix_sync(bf[j], &Bs[wn * 32 + j * 16][ks * 8], 36);
#pragma unroll
            for (int i = 0; i < 4; i++)
#pragma unroll
                for (int j = 0; j < 2; j++)
                    wmma::mma_sync(cf[i][j], af[i], bf[j], cf[i][j]);
        }
    }

#pragma unroll
    for (int i = 0; i < 4; i++) {
        int m0 = bm * 128 + wm * 64 + i * 16;
#pragma unroll
        for (int j = 0; j < 2; j++) {
            int n = bn * 128 + wn * 32 + j * 16;
            if (EPI == 0) {
                // pre-round to tf32 so flash's raw cp.async loads are valid RN tf32
#pragma unroll
                for (int e = 0; e < cf[i][j].num_elements; e++)
                    cf[i][j].x[e] = ftf(cf[i][j].x[e]);
                int b_ = m0 >> 11;
                int t  = m0 & 2047;
                int which = n >> 10;
                int c = n & 1023;
                int head = c >> 6;
                int d = c & 63;
                float* dst = (which == 0) ? g_q : ((which == 1) ? g_k : g_v);
                wmma::store_matrix_sync(
                    &dst[(((size_t)(b_ * NH_ + head)) * TT + t) * HS_ + d],
                    cf[i][j], HS_, wmma::mem_row_major);
            } else {
                wmma::store_matrix_sync(&out[(size_t)m0 * CC + n],
                                        cf[i][j], CC, wmma::mem_row_major);
            }
        }
    }
}

// ---------------------------------------------------------------------------
// Flash attention, register-resident mma.sync tf32.
// Block = (hb, 128-row q-tile), 256 threads = 8 warps; warp w owns rows
// [16w,16w+16). K/V cp.async double-buffered; S + O accumulators in registers;
// only P round-trips smem (warp-private band, __syncwarp only).
// smem: K0|K1|V0|V1 (64x68) | Ss (128x68) = 104448 B.
// ---------------------------------------------------------------------------
#define FLD 68
#define FKV (64 * FLD)
#define FSS (128 * FLD)
#define FLASH_SMEM ((4 * FKV + FSS) * 4)

__global__ __launch_bounds__(256) void flash_mma_kernel()
{
    extern __shared__ float sh[];
    float* Ss = sh + 4 * FKV;

    const int qt = gridDim.x - 1 - blockIdx.x;   // heavy tiles first
    const int hb = blockIdx.y;
    const int tid = threadIdx.x;
    const int warp = tid >> 5;
    const int lane = tid & 31;
    const int g = lane >> 2, tg = lane & 3;
    const int lr = tid >> 2, lq = (tid & 3) * 16;  // K/V loader
    const int rq = tid >> 1, hq = tid & 1;         // Q loader (warp-local rows)

    const int nc = 2 * qt + 2;

    auto issue = [&](int c, int s) {
        const float* kp = g_k + ((size_t)hb * TT + c * 64 + lr) * HS_ + lq;
        const float* vp = g_v + ((size_t)hb * TT + c * 64 + lr) * HS_ + lq;
        unsigned dk = su32(sh + s * FKV + lr * FLD + lq);
        unsigned dv = su32(sh + (2 + s) * FKV + lr * FLD + lq);
#pragma unroll
        for (int u = 0; u < 4; u++) {
            CPA16(dk + u * 16, kp + u * 4);
            CPA16(dv + u * 16, vp + u * 4);
        }
        CPCOMMIT();
    };

    issue(0, 0);

    // ---- stage Q through own Ss band (coalesced), pull into A-frag regs ----
    const float* qp = g_q + ((size_t)hb * TT + qt * 128) * HS_;
    const float qs = 0.125f * 1.44269504f;   // 1/sqrt(64) * log2(e)
#pragma unroll
    for (int u = 0; u < 8; u++) {
        float4 v = *(const float4*)(qp + rq * 64 + hq * 32 + u * 4);
        v.x = ftf(v.x * qs); v.y = ftf(v.y * qs);
        v.z = ftf(v.z * qs); v.w = ftf(v.w * qs);
        *(float4*)&Ss[rq * FLD + hq * 32 + u * 4] = v;
    }
    __syncwarp();
    uint32_t qa[8][4];
    {
        const int r0 = (16 * warp + g) * FLD, r1 = (16 * warp + g + 8) * FLD;
#pragma unroll
        for (int kc = 0; kc < 8; kc++) {
            qa[kc][0] = __float_as_uint(Ss[r0 + 8 * kc + tg]);
            qa[kc][1] = __float_as_uint(Ss[r1 + 8 * kc + tg]);
            qa[kc][2] = __float_as_uint(Ss[r0 + 8 * kc + tg + 4]);
            qa[kc][3] = __float_as_uint(Ss[r1 + 8 * kc + tg + 4]);
        }
    }
    __syncwarp();

    float o[8][4];
#pragma unroll
    for (int j = 0; j < 8; j++)
#pragma unroll
        for (int e = 0; e < 4; e++) o[j][e] = 0.0f;
    float m0 = -1e30f, m1 = -1e30f, l0 = 0.0f, l1 = 0.0f;

    for (int c = 0; c < nc; c++) {
        if (c + 1 < nc) { issue(c + 1, (c + 1) & 1); cpwait<1>(); }
        else            { cpwait<0>(); }
        __syncthreads();
        const float* Ks = sh + (c & 1) * FKV;
        const float* Vs = sh + (2 + (c & 1)) * FKV;

        const int lim = (c >= 2 * qt) ? (16 * warp + 15 - 64 * (c - 2 * qt)) : 127;
        if (lim >= 0) {
            const int jmax = min(7, lim >> 3);

            // ---- S = Q K^T, accumulators in registers ----
            float s[8][4];
#pragma unroll
            for (int j = 0; j < 8; j++)
#pragma unroll
                for (int e = 0; e < 4; e++) s[j][e] = 0.0f;
#pragma unroll
            for (int kc = 0; kc < 8; kc++) {
#pragma unroll
                for (int j = 0; j < 8; j++) {
                    if (j > jmax) break;
                    uint32_t b0 = __float_as_uint(Ks[(8 * j + g) * FLD + 8 * kc + tg]);
                    uint32_t b1 = __float_as_uint(Ks[(8 * j + g) * FLD + 8 * kc + tg + 4]);
                    mma_tf32(s[j], qa[kc][0], qa[kc][1], qa[kc][2], qa[kc][3], b0, b1);
                }
            }

            // ---- causal mask in registers ----
            if (c >= 2 * qt) {
                const int kb = 64 * (c - 2 * qt);
                const int row0 = 16 * warp + g, row1 = row0 + 8;
#pragma unroll
                for (int j = 0; j < 8; j++) {
                    if (j > jmax) break;
                    int col = kb + 8 * j + 2 * tg;
                    if (col     > row0) s[j][0] = -1e30f;
                    if (col + 1 > row0) s[j][1] = -1e30f;
                    if (col     > row1) s[j][2] = -1e30f;
                    if (col + 1 > row1) s[j][3] = -1e30f;
                }
            }

            // ---- online softmax on registers (rows g and g+8) ----
            float rm0 = -1e30f, rm1 = -1e30f;
#pragma unroll
            for (int j = 0; j < 8; j++) {
                if (j > jmax) break;
                rm0 = fmaxf(rm0, fmaxf(s[j][0], s[j][1]));
                rm1 = fmaxf(rm1, fmaxf(s[j][2], s[j][3]));
            }
            rm0 = fmaxf(rm0, __shfl_xor_sync(0xffffffffu, rm0, 1));
            rm0 = fmaxf(rm0, __shfl_xor_sync(0xffffffffu, rm0, 2));
            rm1 = fmaxf(rm1, __shfl_xor_sync(0xffffffffu, rm1, 1));
            rm1 = fmaxf(rm1, __shfl_xor_sync(0xffffffffu, rm1, 2));
            float mn0 = fmaxf(m0, rm0), mn1 = fmaxf(m1, rm1);
            float corr0 = ex2(m0 - mn0), corr1 = ex2(m1 - mn1);
            float rs0 = 0.0f, rs1 = 0.0f;
#pragma unroll
            for (int j = 0; j < 8; j++) {
                if (j > jmax) break;
                s[j][0] = ex2(s[j][0] - mn0); rs0 += s[j][0];
                s[j][1] = ex2(s[j][1] - mn0); rs0 += s[j][1];
                s[j][2] = ex2(s[j][2] - mn1); rs1 += s[j][2];
                s[j][3] = ex2(s[j][3] - mn1); rs1 += s[j][3];
            }
            rs0 += __shfl_xor_sync(0xffffffffu, rs0, 1);
            rs0 += __shfl_xor_sync(0xffffffffu, rs0, 2);
            rs1 += __shfl_xor_sync(0xffffffffu, rs1, 1);
            rs1 += __shfl_xor_sync(0xffffffffu, rs1, 2);
            l0 = l0 * corr0 + rs0; m0 = mn0;
            l1 = l1 * corr1 + rs1; m1 = mn1;
#pragma unroll
            for (int j = 0; j < 8; j++) {
                o[j][0] *= corr0; o[j][1] *= corr0;
                o[j][2] *= corr1; o[j][3] *= corr1;
            }

            // ---- P to warp-private smem band (tf32-rounded) ----
            const int pr0 = (16 * warp + g) * FLD, pr1 = (16 * warp + g + 8) * FLD;
#pragma unroll
            for (int j = 0; j < 8; j++) {
                if (j > jmax) break;
                *(float2*)&Ss[pr0 + 8 * j + 2 * tg] =
                    make_float2(ftf(s[j][0]), ftf(s[j][1]));
                *(float2*)&Ss[pr1 + 8 * j + 2 * tg] =
                    make_float2(ftf(s[j][2]), ftf(s[j][3]));
            }
            __syncwarp();

            // ---- O += P @ V (O stays in registers across chunks) ----
#pragma unroll
            for (int kc = 0; kc < 8; kc++) {
                if (kc > jmax) break;
                uint32_t pa0 = __float_as_uint(Ss[pr0 + 8 * kc + tg]);
                uint32_t pa1 = __float_as_uint(Ss[pr1 + 8 * kc + tg]);
                uint32_t pa2 = __float_as_uint(Ss[pr0 + 8 * kc + tg + 4]);
                uint32_t pa3 = __float_as_uint(Ss[pr1 + 8 * kc + tg + 4]);
#pragma unroll
                for (int j = 0; j < 8; j++) {
                    uint32_t b0 = __float_as_uint(Vs[(8 * kc + tg) * FLD + 8 * j + g]);
                    uint32_t b1 = __float_as_uint(Vs[(8 * kc + tg + 4) * FLD + 8 * j + g]);
                    mma_tf32(o[j], pa0, pa1, pa2, pa3, b0, b1);
                }
            }
            __syncwarp();
        }
        __syncthreads();   // stage reuse protection
    }

    // ---- write O in [B,T,NH,HS] layout ----
    const float inv0 = 1.0f / l0, inv1 = 1.0f / l1;
    const int b_ = hb >> 4, head = hb & 15;
    const int t0 = qt * 128 + 16 * warp + g, t1 = t0 + 8;
    float* y0 = g_y + (((size_t)(b_ * TT + t0)) * NH_ + head) * HS_;
    float* y1 = g_y + (((size_t)(b_ * TT + t1)) * NH_ + head) * HS_;
#pragma unroll
    for (int j = 0; j < 8; j++) {
        *(float2*)&y0[8 * j + 2 * tg] = make_float2(o[j][0] * inv0, o[j][1] * inv0);
        *(float2*)&y1[8 * j + 2 * tg] = make_float2(o[j][2] * inv1, o[j][3] * inv1);
    }
}

// ---------------------------------------------------------------------------
extern "C" void kernel_launch(void* const* d_in, const int* in_sizes, int n_in,
                              void* d_out, int out_size)
{
    const float* x      = (const float*)d_in[0];  // [B,T,C]
    const float* W_attn = (const float*)d_in[1];  // [3C,C]
    const float* W_proj = (const float*)d_in[2];  // [C,C]
    // d_in[3..6] feed a discarded branch — skipped.
    float* out = (float*)d_out;                   // [B,T,C] fp32

    cudaFuncSetAttribute(flash_mma_kernel,
                         cudaFuncAttributeMaxDynamicSharedMemorySize, FLASH_SMEM);

    gemm_tf32_kernel<0><<<dim3(3 * CC / 128, BB * TT / 128), 256>>>(x, W_attn, nullptr);
    flash_mma_kernel<<<dim3(TT / 128, HB_), 256, FLASH_SMEM>>>();
    gemm_tf32_kernel<1><<<dim3(CC / 128, BB * TT / 128), 256>>>(x, W_proj, out);
}

// round 8
// speedup vs baseline: 1.9370x; 1.5880x over previous
#include <cuda_runtime.h>
#include <mma.h>
#include <cstdint>
using namespace nvcuda;

#define BB  4
#define TT  2048
#define CC  1024
#define NH_ 16
#define HS_ 64
#define HB_ (BB * NH_)   // 64 (b,h) pairs

// Scratch (device globals — no allocation allowed)
__device__ float g_q[(size_t)BB * NH_ * TT * HS_];   // [B,NH,T,HS], tf32-rounded
__device__ float g_k[(size_t)BB * NH_ * TT * HS_];
__device__ float g_v[(size_t)BB * NH_ * TT * HS_];
__device__ float g_y[(size_t)BB * TT * CC];          // [B,T,NH,HS] == [B,T,C]

__device__ __forceinline__ float ftf(float x) { return wmma::__float_to_tf32(x); }
__device__ __forceinline__ float4 ftf4(float4 v) {
    return make_float4(ftf(v.x), ftf(v.y), ftf(v.z), ftf(v.w));
}
__device__ __forceinline__ float ex2(float x) {
    float r; asm("ex2.approx.ftz.f32 %0, %1;" : "=f"(r) : "f"(x)); return r;
}
__device__ __forceinline__ unsigned su32(const void* p) {
    return (unsigned)__cvta_generic_to_shared(p);
}
#define CPA16(dst, src) \
    asm volatile("cp.async.cg.shared.global [%0], [%1], 16;" :: "r"(dst), "l"(src))
#define CPCOMMIT() asm volatile("cp.async.commit_group;")
template<int N> __device__ __forceinline__ void cpwait() {
    asm volatile("cp.async.wait_group %0;" :: "n"(N));
}

// Raw tf32 MMA m16n8k8 (lane l: g=l>>2, tg=l&3):
//   A: a0=(g,tg) a1=(g+8,tg) a2=(g,tg+4) a3=(g+8,tg+4)
//   B: b0=(k=tg,n=g) b1=(k=tg+4,n=g)
//   C: c0=(g,2tg) c1=(g,2tg+1) c2=(g+8,2tg) c3=(g+8,2tg+1)
__device__ __forceinline__ void mma_tf32(float* d,
    uint32_t a0, uint32_t a1, uint32_t a2, uint32_t a3,
    uint32_t b0, uint32_t b1)
{
    asm volatile("mma.sync.aligned.m16n8k8.row.col.f32.tf32.tf32.f32 "
        "{%0,%1,%2,%3}, {%4,%5,%6,%7}, {%8,%9}, {%0,%1,%2,%3};"
        : "+f"(d[0]), "+f"(d[1]), "+f"(d[2]), "+f"(d[3])
        : "r"(a0), "r"(a1), "r"(a2), "r"(a3), "r"(b0), "r"(b1));
}

__device__ __forceinline__ void ldsm_x4(uint32_t& r0, uint32_t& r1,
                                        uint32_t& r2, uint32_t& r3, uint32_t addr)
{
    asm volatile("ldmatrix.sync.aligned.m8n8.x4.shared.b16 {%0,%1,%2,%3}, [%4];"
        : "=r"(r0), "=r"(r1), "=r"(r2), "=r"(r3) : "r"(addr));
}

// ---------------------------------------------------------------------------
// TF32 GEMM, raw mma + ldmatrix: C = A @ W^T.
// Block 128x128, BK=32, 256 threads = 8 warps (2m x 4n), warp tile 64x32.
// tf32-converted at smem store. ldmatrix lane mapping (f32-as-b16-pairs):
//  A x4 quadrants: (rows0-7,k0-3)(rows8-15,k0-3)(rows0-7,k4-7)(rows8-15,k4-7)
//   -> lane rows: (l&7) + ((l>>3)&1)*8, col group ((l>>4)&1)*4
//  B x4 over a 16-n-row, 8-k tile: (n0-7,k0-3)(n0-7,k4-7)(n8-15,k0-3)(n8-15,k4-7)
//   -> lane rows: (l&7) + ((l>>4)&1)*8, col group ((l>>3)&1)*4
// EPI==0: scatter tf32-rounded q/k/v; EPI==1: plain fp32 store from g_y.
// ---------------------------------------------------------------------------
template<int EPI>
__global__ __launch_bounds__(256, 2) void gemm_tf32_kernel(
    const float* __restrict__ A, const float* __restrict__ W,
    float* __restrict__ out)
{
    __shared__ __align__(16) float As[128][36];
    __shared__ __align__(16) float Bs[128][36];

    const int tid = threadIdx.x;
    const int bn = blockIdx.x, bm = blockIdx.y;
    const int warp = tid >> 5;
    const int lane = tid & 31;
    const int g = lane >> 2, tg = lane & 3;
    const int wm = warp >> 2, wn = warp & 3;       // 2m x 4n warps
    const int lrow = tid >> 1, lcol = (tid & 1) * 16;

    // per-lane ldmatrix element offsets (relative to tile origin, in floats)
    const int aoff = ((lane & 7) + ((lane >> 3) & 1) * 8) * 36 + ((lane >> 4) & 1) * 4;
    const int boff = ((lane & 7) + ((lane >> 4) & 1) * 8) * 36 + ((lane >> 3) & 1) * 4;

    float c[4][4][4];
#pragma unroll
    for (int i = 0; i < 4; i++)
#pragma unroll
        for (int j = 0; j < 4; j++)
#pragma unroll
            for (int e = 0; e < 4; e++) c[i][j][e] = 0.0f;

    const float* Asrc = (EPI == 1) ? (const float*)g_y : A;
    const float* Ab = Asrc + (size_t)(bm * 128 + lrow) * CC + lcol;
    const float* Wb = W + (size_t)(bn * 128 + lrow) * CC + lcol;

    const uint32_t asb = su32(&As[0][0]);
    const uint32_t bsb = su32(&Bs[0][0]);

    for (int k0 = 0; k0 < CC; k0 += 32) {
        float4 a[4], b[4];
#pragma unroll
        for (int u = 0; u < 4; u++) {
            a[u] = *(const float4*)(Ab + k0 + u * 4);
            b[u] = *(const float4*)(Wb + k0 + u * 4);
        }
        __syncthreads();
#pragma unroll
        for (int u = 0; u < 4; u++) {
            *(float4*)&As[lrow][lcol + u * 4] = ftf4(a[u]);
            *(float4*)&Bs[lrow][lcol + u * 4] = ftf4(b[u]);
        }
        __syncthreads();
#pragma unroll
        for (int ks = 0; ks < 4; ks++) {
            uint32_t af[4][4], bf[2][4];
#pragma unroll
            for (int i = 0; i < 4; i++)
                ldsm_x4(af[i][0], af[i][1], af[i][2], af[i][3],
                        asb + 4 * ((wm * 64 + i * 16) * 36 + ks * 8 + aoff));
#pragma unroll
            for (int j2 = 0; j2 < 2; j2++)
                ldsm_x4(bf[j2][0], bf[j2][1], bf[j2][2], bf[j2][3],
                        bsb + 4 * ((wn * 32 + j2 * 16) * 36 + ks * 8 + boff));
#pragma unroll
            for (int i = 0; i < 4; i++)
#pragma unroll
                for (int j = 0; j < 4; j++)
                    mma_tf32(c[i][j], af[i][0], af[i][1], af[i][2], af[i][3],
                             bf[j >> 1][(j & 1) * 2], bf[j >> 1][(j & 1) * 2 + 1]);
        }
    }

    // Epilogue: c[i][j] layout c0=(g,2tg) c1=(g,2tg+1) c2=(g+8,2tg) c3=(g+8,2tg+1)
#pragma unroll
    for (int i = 0; i < 4; i++) {
        int mA = bm * 128 + wm * 64 + i * 16 + g;
        int mB = mA + 8;
#pragma unroll
        for (int j = 0; j < 4; j++) {
            int n = bn * 128 + wn * 32 + j * 8 + 2 * tg;
            if (EPI == 0) {
                int which = n >> 10;
                int cc = n & 1023;
                int head = cc >> 6, d = cc & 63;
                float* dst = (which == 0) ? g_q : ((which == 1) ? g_k : g_v);
                int bA = mA >> 11, tA = mA & 2047;
                int bB = mB >> 11, tB = mB & 2047;
                *(float2*)&dst[(((size_t)(bA * NH_ + head)) * TT + tA) * HS_ + d] =
                    make_float2(ftf(c[i][j][0]), ftf(c[i][j][1]));
                *(float2*)&dst[(((size_t)(bB * NH_ + head)) * TT + tB) * HS_ + d] =
                    make_float2(ftf(c[i][j][2]), ftf(c[i][j][3]));
            } else {
                *(float2*)&out[(size_t)mA * CC + n] = make_float2(c[i][j][0], c[i][j][1]);
                *(float2*)&out[(size_t)mB * CC + n] = make_float2(c[i][j][2], c[i][j][3]);
            }
        }
    }
}

// ---------------------------------------------------------------------------
// Flash attention (unchanged from R7 — proven): register-resident mma.sync.
// ---------------------------------------------------------------------------
#define FLD 68
#define FKV (64 * FLD)
#define FSS (128 * FLD)
#define FLASH_SMEM ((4 * FKV + FSS) * 4)

__global__ __launch_bounds__(256) void flash_mma_kernel()
{
    extern __shared__ float sh[];
    float* Ss = sh + 4 * FKV;

    const int qt = gridDim.x - 1 - blockIdx.x;
    const int hb = blockIdx.y;
    const int tid = threadIdx.x;
    const int warp = tid >> 5;
    const int lane = tid & 31;
    const int g = lane >> 2, tg = lane & 3;
    const int lr = tid >> 2, lq = (tid & 3) * 16;
    const int rq = tid >> 1, hq = tid & 1;

    const int nc = 2 * qt + 2;

    auto issue = [&](int c, int s) {
        const float* kp = g_k + ((size_t)hb * TT + c * 64 + lr) * HS_ + lq;
        const float* vp = g_v + ((size_t)hb * TT + c * 64 + lr) * HS_ + lq;
        unsigned dk = su32(sh + s * FKV + lr * FLD + lq);
        unsigned dv = su32(sh + (2 + s) * FKV + lr * FLD + lq);
#pragma unroll
        for (int u = 0; u < 4; u++) {
            CPA16(dk + u * 16, kp + u * 4);
            CPA16(dv + u * 16, vp + u * 4);
        }
        CPCOMMIT();
    };

    issue(0, 0);

    const float* qp = g_q + ((size_t)hb * TT + qt * 128) * HS_;
    const float qs = 0.125f * 1.44269504f;
#pragma unroll
    for (int u = 0; u < 8; u++) {
        float4 v = *(const float4*)(qp + rq * 64 + hq * 32 + u * 4);
        v.x = ftf(v.x * qs); v.y = ftf(v.y * qs);
        v.z = ftf(v.z * qs); v.w = ftf(v.w * qs);
        *(float4*)&Ss[rq * FLD + hq * 32 + u * 4] = v;
    }
    __syncwarp();
    uint32_t qa[8][4];
    {
        const int r0 = (16 * warp + g) * FLD, r1 = (16 * warp + g + 8) * FLD;
#pragma unroll
        for (int kc = 0; kc < 8; kc++) {
            qa[kc][0] = __float_as_uint(Ss[r0 + 8 * kc + tg]);
            qa[kc][1] = __float_as_uint(Ss[r1 + 8 * kc + tg]);
            qa[kc][2] = __float_as_uint(Ss[r0 + 8 * kc + tg + 4]);
            qa[kc][3] = __float_as_uint(Ss[r1 + 8 * kc + tg + 4]);
        }
    }
    __syncwarp();

    float o[8][4];
#pragma unroll
    for (int j = 0; j < 8; j++)
#pragma unroll
        for (int e = 0; e < 4; e++) o[j][e] = 0.0f;
    float m0 = -1e30f, m1 = -1e30f, l0 = 0.0f, l1 = 0.0f;

    for (int c = 0; c < nc; c++) {
        if (c + 1 < nc) { issue(c + 1, (c + 1) & 1); cpwait<1>(); }
        else            { cpwait<0>(); }
        __syncthreads();
        const float* Ks = sh + (c & 1) * FKV;
        const float* Vs = sh + (2 + (c & 1)) * FKV;

        const int lim = (c >= 2 * qt) ? (16 * warp + 15 - 64 * (c - 2 * qt)) : 127;
        if (lim >= 0) {
            const int jmax = min(7, lim >> 3);

            float s[8][4];
#pragma unroll
            for (int j = 0; j < 8; j++)
#pragma unroll
                for (int e = 0; e < 4; e++) s[j][e] = 0.0f;
#pragma unroll
            for (int kc = 0; kc < 8; kc++) {
#pragma unroll
                for (int j = 0; j < 8; j++) {
                    if (j > jmax) break;
                    uint32_t b0 = __float_as_uint(Ks[(8 * j + g) * FLD + 8 * kc + tg]);
                    uint32_t b1 = __float_as_uint(Ks[(8 * j + g) * FLD + 8 * kc + tg + 4]);
                    mma_tf32(s[j], qa[kc][0], qa[kc][1], qa[kc][2], qa[kc][3], b0, b1);
                }
            }

            if (c >= 2 * qt) {
                const int kb = 64 * (c - 2 * qt);
                const int row0 = 16 * warp + g, row1 = row0 + 8;
#pragma unroll
                for (int j = 0; j < 8; j++) {
                    if (j > jmax) break;
                    int col = kb + 8 * j + 2 * tg;
                    if (col     > row0) s[j][0] = -1e30f;
                    if (col + 1 > row0) s[j][1] = -1e30f;
                    if (col     > row1) s[j][2] = -1e30f;
                    if (col + 1 > row1) s[j][3] = -1e30f;
                }
            }

            float rm0 = -1e30f, rm1 = -1e30f;
#pragma unroll
            for (int j = 0; j < 8; j++) {
                if (j > jmax) break;
                rm0 = fmaxf(rm0, fmaxf(s[j][0], s[j][1]));
                rm1 = fmaxf(rm1, fmaxf(s[j][2], s[j][3]));
            }
            rm0 = fmaxf(rm0, __shfl_xor_sync(0xffffffffu, rm0, 1));
            rm0 = fmaxf(rm0, __shfl_xor_sync(0xffffffffu, rm0, 2));
            rm1 = fmaxf(rm1, __shfl_xor_sync(0xffffffffu, rm1, 1));
            rm1 = fmaxf(rm1, __shfl_xor_sync(0xffffffffu, rm1, 2));
            float mn0 = fmaxf(m0, rm0), mn1 = fmaxf(m1, rm1);
            float corr0 = ex2(m0 - mn0), corr1 = ex2(m1 - mn1);
            float rs0 = 0.0f, rs1 = 0.0f;
#pragma unroll
            for (int j = 0; j < 8; j++) {
                if (j > jmax) break;
                s[j][0] = ex2(s[j][0] - mn0); rs0 += s[j][0];
                s[j][1] = ex2(s[j][1] - mn0); rs0 += s[j][1];
                s[j][2] = ex2(s[j][2] - mn1); rs1 += s[j][2];
                s[j][3] = ex2(s[j][3] - mn1); rs1 += s[j][3];
            }
            rs0 += __shfl_xor_sync(0xffffffffu, rs0, 1);
            rs0 += __shfl_xor_sync(0xffffffffu, rs0, 2);
            rs1 += __shfl_xor_sync(0xffffffffu, rs1, 1);
            rs1 += __shfl_xor_sync(0xffffffffu, rs1, 2);
            l0 = l0 * corr0 + rs0; m0 = mn0;
            l1 = l1 * corr1 + rs1; m1 = mn1;
#pragma unroll
            for (int j = 0; j < 8; j++) {
                o[j][0] *= corr0; o[j][1] *= corr0;
                o[j][2] *= corr1; o[j][3] *= corr1;
            }

            const int pr0 = (16 * warp + g) * FLD, pr1 = (16 * warp + g + 8) * FLD;
#pragma unroll
            for (int j = 0; j < 8; j++) {
                if (j > jmax) break;
                *(float2*)&Ss[pr0 + 8 * j + 2 * tg] =
                    make_float2(ftf(s[j][0]), ftf(s[j][1]));
                *(float2*)&Ss[pr1 + 8 * j + 2 * tg] =
                    make_float2(ftf(s[j][2]), ftf(s[j][3]));
            }
            __syncwarp();

#pragma unroll
            for (int kc = 0; kc < 8; kc++) {
                if (kc > jmax) break;
                uint32_t pa0 = __float_as_uint(Ss[pr0 + 8 * kc + tg]);
                uint32_t pa1 = __float_as_uint(Ss[pr1 + 8 * kc + tg]);
                uint32_t pa2 = __float_as_uint(Ss[pr0 + 8 * kc + tg + 4]);
                uint32_t pa3 = __float_as_uint(Ss[pr1 + 8 * kc + tg + 4]);
#pragma unroll
                for (int j = 0; j < 8; j++) {
                    uint32_t b0 = __float_as_uint(Vs[(8 * kc + tg) * FLD + 8 * j + g]);
                    uint32_t b1 = __float_as_uint(Vs[(8 * kc + tg + 4) * FLD + 8 * j + g]);
                    mma_tf32(o[j], pa0, pa1, pa2, pa3, b0, b1);
                }
            }
            __syncwarp();
        }
        __syncthreads();
    }

    const float inv0 = 1.0f / l0, inv1 = 1.0f / l1;
    const int b_ = hb >> 4, head = hb & 15;
    const int t0 = qt * 128 + 16 * warp + g, t1 = t0 + 8;
    float* y0 = g_y + (((size_t)(b_ * TT + t0)) * NH_ + head) * HS_;
    float* y1 = g_y + (((size_t)(b_ * TT + t1)) * NH_ + head) * HS_;
#pragma unroll
    for (int j = 0; j < 8; j++) {
        *(float2*)&y0[8 * j + 2 * tg] = make_float2(o[j][0] * inv0, o[j][1] * inv0);
        *(float2*)&y1[8 * j + 2 * tg] = make_float2(o[j][2] * inv1, o[j][3] * inv1);
    }
}

// ---------------------------------------------------------------------------
extern "C" void kernel_launch(void* const* d_in, const int* in_sizes, int n_in,
                              void* d_out, int out_size)
{
    const float* x      = (const float*)d_in[0];  // [B,T,C]
    const float* W_attn = (const float*)d_in[1];  // [3C,C]
    const float* W_proj = (const float*)d_in[2];  // [C,C]
    // d_in[3..6] feed a discarded branch — skipped.
    float* out = (float*)d_out;                   // [B,T,C] fp32

    cudaFuncSetAttribute(flash_mma_kernel,
                         cudaFuncAttributeMaxDynamicSharedMemorySize, FLASH_SMEM);

    gemm_tf32_kernel<0><<<dim3(3 * CC / 128, BB * TT / 128), 256>>>(x, W_attn, nullptr);
    flash_mma_kernel<<<dim3(TT / 128, HB_), 256, FLASH_SMEM>>>();
    gemm_tf32_kernel<1><<<dim3(CC / 128, BB * TT / 128), 256>>>(x, W_proj, out);
}

// round 9
// speedup vs baseline: 2.1118x; 1.0902x over previous
#include <cuda_runtime.h>
#include <mma.h>
#include <cstdint>
using namespace nvcuda;

#define BB  4
#define TT  2048
#define CC  1024
#define NH_ 16
#define HS_ 64
#define HB_ (BB * NH_)   // 64 (b,h) pairs

// Scratch (device globals — no allocation allowed)
__device__ float g_q[(size_t)BB * NH_ * TT * HS_];   // [B,NH,t,d], tf32
__device__ float g_k[(size_t)BB * NH_ * TT * HS_];   // [B,NH,t,d], tf32
__device__ float g_v[(size_t)BB * NH_ * TT * HS_];   // [B,NH,d,t] TRANSPOSED, tf32
__device__ float g_y[(size_t)BB * TT * CC];          // [B,T,NH,HS], tf32
__device__ float g_xr[(size_t)BB * TT * CC];         // tf32-rounded x
__device__ float g_wr[(size_t)3 * CC * CC];          // tf32-rounded W_attn
__device__ float g_wpr[(size_t)CC * CC];             // tf32-rounded W_proj

__device__ __forceinline__ float ftf(float x) { return wmma::__float_to_tf32(x); }
__device__ __forceinline__ float ex2(float x) {
    float r; asm("ex2.approx.ftz.f32 %0, %1;" : "=f"(r) : "f"(x)); return r;
}
__device__ __forceinline__ unsigned su32(const void* p) {
    return (unsigned)__cvta_generic_to_shared(p);
}
#define CPA16(dst, src) \
    asm volatile("cp.async.cg.shared.global [%0], [%1], 16;" :: "r"(dst), "l"(src))
#define CPCOMMIT() asm volatile("cp.async.commit_group;")
template<int N> __device__ __forceinline__ void cpwait() {
    asm volatile("cp.async.wait_group %0;" :: "n"(N));
}

// Raw tf32 MMA m16n8k8 (lane l: g=l>>2, tg=l&3):
//   A: a0=(g,tg) a1=(g+8,tg) a2=(g,tg+4) a3=(g+8,tg+4)
//   B: b0=(k=tg,n=g) b1=(k=tg+4,n=g)
//   C: c0=(g,2tg) c1=(g,2tg+1) c2=(g+8,2tg) c3=(g+8,2tg+1)
__device__ __forceinline__ void mma_tf32(float* d,
    uint32_t a0, uint32_t a1, uint32_t a2, uint32_t a3,
    uint32_t b0, uint32_t b1)
{
    asm volatile("mma.sync.aligned.m16n8k8.row.col.f32.tf32.tf32.f32 "
        "{%0,%1,%2,%3}, {%4,%5,%6,%7}, {%8,%9}, {%0,%1,%2,%3};"
        : "+f"(d[0]), "+f"(d[1]), "+f"(d[2]), "+f"(d[3])
        : "r"(a0), "r"(a1), "r"(a2), "r"(a3), "r"(b0), "r"(b1));
}

__device__ __forceinline__ void ldsm_x4(uint32_t& r0, uint32_t& r1,
                                        uint32_t& r2, uint32_t& r3, uint32_t addr)
{
    asm volatile("ldmatrix.sync.aligned.m8n8.x4.shared.b16 {%0,%1,%2,%3}, [%4];"
        : "=r"(r0), "=r"(r1), "=r"(r2), "=r"(r3) : "r"(addr));
}

// Per-lane ldmatrix row-address offsets (floats, relative to tile origin).
// A-tile [16 rows][k] stride S: quadrants (r0-7,k0-3)(r8-15,k0-3)(r0-7,k4-7)(r8-15,k4-7)
#define AOFF(S) ((((lane & 7) + ((lane >> 3) & 1) * 8) * (S)) + ((lane >> 4) & 1) * 4)
// B-tile [16 n][k] stride S: quadrants (n0-7,k0-3)(n0-7,k4-7)(n8-15,k0-3)(n8-15,k4-7)
#define BOFF(S) ((((lane & 7) + ((lane >> 4) & 1) * 8) * (S)) + ((lane >> 3) & 1) * 4)

// ---------------------------------------------------------------------------
// tf32 RN pre-round pass
// ---------------------------------------------------------------------------
__global__ void tf32_round_kernel(const float* __restrict__ src,
                                  float* __restrict__ dst, int n4)
{
    int i = blockIdx.x * blockDim.x + threadIdx.x;
    if (i < n4) {
        float4 v = ((const float4*)src)[i];
        v.x = ftf(v.x); v.y = ftf(v.y); v.z = ftf(v.z); v.w = ftf(v.w);
        ((float4*)dst)[i] = v;
    }
}

// ---------------------------------------------------------------------------
// TF32 GEMM, cp.async 2-stage + ldmatrix + raw mma: C = A @ W^T.
// Inputs pre-rounded tf32. Block 128x128, BK=32, 256 threads = 8 warps
// (2m x 4n), warp tile 64x32.
// EPI==0: scatter q/k ([B,NH,t,d]) and v TRANSPOSED ([B,NH,d,t]), ftf-rounded.
// EPI==1: A := g_y, plain fp32 store.
// ---------------------------------------------------------------------------
#define GLD 36
#define GT (128 * GLD)
#define GEMM_SMEM (4 * GT * 4)   // 73728 B

template<int EPI>
__global__ __launch_bounds__(256, 2) void gemm_tf32_kernel(
    const float* __restrict__ A, const float* __restrict__ W,
    float* __restrict__ out)
{
    extern __shared__ __align__(16) float sh[];   // [s0A|s0B|s1A|s1B]

    const int tid = threadIdx.x;
    const int bn = blockIdx.x, bm = blockIdx.y;
    const int warp = tid >> 5;
    const int lane = tid & 31;
    const int g = lane >> 2, tg = lane & 3;
    const int wm = warp >> 2, wn = warp & 3;
    const int lrow = tid >> 1, lcol = (tid & 1) * 16;

    const int aoff = AOFF(GLD);
    const int boff = BOFF(GLD);

    float c[4][4][4];
#pragma unroll
    for (int i = 0; i < 4; i++)
#pragma unroll
        for (int j = 0; j < 4; j++)
#pragma unroll
            for (int e = 0; e < 4; e++) c[i][j][e] = 0.0f;

    const float* Asrc = (EPI == 1) ? (const float*)g_y : A;
    const float* Ag = Asrc + (size_t)(bm * 128 + lrow) * CC + lcol;
    const float* Wg = W + (size_t)(bn * 128 + lrow) * CC + lcol;
    const uint32_t shb = su32(sh);

    auto issue = [&](int it, int s) {
        uint32_t da = shb + 4 * (s * 2 * GT + lrow * GLD + lcol);
        uint32_t db = da + 4 * GT;
        const float* ga = Ag + it * 32;
        const float* gb = Wg + it * 32;
#pragma unroll
        for (int u = 0; u < 4; u++) {
            CPA16(da + u * 16, ga + u * 4);
            CPA16(db + u * 16, gb + u * 4);
        }
        CPCOMMIT();
    };

    issue(0, 0);
    const int NIT = CC / 32;
    for (int it = 0; it < NIT; it++) {
        if (it + 1 < NIT) { issue(it + 1, (it + 1) & 1); cpwait<1>(); }
        else              { cpwait<0>(); }
        __syncthreads();
        const uint32_t asb = shb + 4 * ((it & 1) * 2 * GT);
        const uint32_t bsb = asb + 4 * GT;
#pragma unroll
        for (int ks = 0; ks < 4; ks++) {
            uint32_t af[4][4], bf[2][4];
#pragma unroll
            for (int i = 0; i < 4; i++)
                ldsm_x4(af[i][0], af[i][1], af[i][2], af[i][3],
                        asb + 4 * ((wm * 64 + i * 16) * GLD + ks * 8 + aoff));
#pragma unroll
            for (int j2 = 0; j2 < 2; j2++)
                ldsm_x4(bf[j2][0], bf[j2][1], bf[j2][2], bf[j2][3],
                        bsb + 4 * ((wn * 32 + j2 * 16) * GLD + ks * 8 + boff));
#pragma unroll
            for (int i = 0; i < 4; i++)
#pragma unroll
                for (int j = 0; j < 4; j++)
                    mma_tf32(c[i][j], af[i][0], af[i][1], af[i][2], af[i][3],
                             bf[j >> 1][(j & 1) * 2], bf[j >> 1][(j & 1) * 2 + 1]);
        }
        __syncthreads();
    }

#pragma unroll
    for (int i = 0; i < 4; i++) {
        int mA = bm * 128 + wm * 64 + i * 16 + g;
        int mB = mA + 8;
#pragma unroll
        for (int j = 0; j < 4; j++) {
            int n = bn * 128 + wn * 32 + j * 8 + 2 * tg;
            if (EPI == 0) {
                int which = n >> 10;
                int cc = n & 1023;
                int head = cc >> 6, d = cc & 63;
                int bA = mA >> 11, tA = mA & 2047;
                int bB = mB >> 11, tB = mB & 2047;
                if (which == 2) {   // v: transposed [B,NH,d,t]
                    float* base = g_v + ((size_t)(bA * NH_ + head) * HS_) * TT;
                    base[(size_t)(d    ) * TT + tA] = ftf(c[i][j][0]);
                    base[(size_t)(d + 1) * TT + tA] = ftf(c[i][j][1]);
                    float* baseB = g_v + ((size_t)(bB * NH_ + head) * HS_) * TT;
                    baseB[(size_t)(d    ) * TT + tB] = ftf(c[i][j][2]);
                    baseB[(size_t)(d + 1) * TT + tB] = ftf(c[i][j][3]);
                } else {
                    float* dst = (which == 0) ? g_q : g_k;
                    *(float2*)&dst[(((size_t)(bA * NH_ + head)) * TT + tA) * HS_ + d] =
                        make_float2(ftf(c[i][j][0]), ftf(c[i][j][1]));
                    *(float2*)&dst[(((size_t)(bB * NH_ + head)) * TT + tB) * HS_ + d] =
                        make_float2(ftf(c[i][j][2]), ftf(c[i][j][3]));
                }
            } else {
                *(float2*)&out[(size_t)mA * CC + n] = make_float2(c[i][j][0], c[i][j][1]);
                *(float2*)&out[(size_t)mB * CC + n] = make_float2(c[i][j][2], c[i][j][3]);
            }
        }
    }
}

// ---------------------------------------------------------------------------
// Flash attention: register-resident mma.sync, ldmatrix fragment loads.
// Block = (hb, 128-row q-tile), 256 threads = 8 warps; warp w owns rows
// [16w,16w+16). K [key][d]; V TRANSPOSED [d][key] (from g_v layout).
// smem: K0|K1|V0|V1 (64x68) | Ss (128x68).
// ---------------------------------------------------------------------------
#define FLD 68
#define FKV (64 * FLD)
#define FSS (128 * FLD)
#define FLASH_SMEM ((4 * FKV + FSS) * 4)

__global__ __launch_bounds__(256) void flash_mma_kernel()
{
    extern __shared__ __align__(16) float sh[];
    float* Ss = sh + 4 * FKV;

    const int qt = gridDim.x - 1 - blockIdx.x;   // heavy tiles first
    const int hb = blockIdx.y;
    const int tid = threadIdx.x;
    const int warp = tid >> 5;
    const int lane = tid & 31;
    const int g = lane >> 2, tg = lane & 3;
    const int lr = tid >> 2, lq = (tid & 3) * 16;
    const int rq = tid >> 1, hq = tid & 1;

    const int aoff = AOFF(FLD);
    const int boff = BOFF(FLD);
    const int nc = 2 * qt + 2;

    auto issue = [&](int c, int s) {
        const float* kp = g_k + ((size_t)hb * TT + c * 64 + lr) * HS_ + lq;
        const float* vp = g_v + ((size_t)hb * HS_ + lr) * TT + c * 64 + lq;  // [d][t]
        unsigned dk = su32(sh + s * FKV + lr * FLD + lq);
        unsigned dv = su32(sh + (2 + s) * FKV + lr * FLD + lq);
#pragma unroll
        for (int u = 0; u < 4; u++) {
            CPA16(dk + u * 16, kp + u * 4);
            CPA16(dv + u * 16, vp + u * 4);
        }
        CPCOMMIT();
    };

    issue(0, 0);

    // ---- stage Q through own Ss band, pull A-frags via ldmatrix ----
    const float* qp = g_q + ((size_t)hb * TT + qt * 128) * HS_;
    const float qs = 0.125f * 1.44269504f;
#pragma unroll
    for (int u = 0; u < 8; u++) {
        float4 v = *(const float4*)(qp + rq * 64 + hq * 32 + u * 4);
        v.x = ftf(v.x * qs); v.y = ftf(v.y * qs);
        v.z = ftf(v.z * qs); v.w = ftf(v.w * qs);
        *(float4*)&Ss[rq * FLD + hq * 32 + u * 4] = v;
    }
    __syncwarp();
    const uint32_t ssb = su32(Ss);
    uint32_t qa[8][4];
#pragma unroll
    for (int kc = 0; kc < 8; kc++)
        ldsm_x4(qa[kc][0], qa[kc][1], qa[kc][2], qa[kc][3],
                ssb + 4 * ((16 * warp) * FLD + 8 * kc + aoff));
    __syncwarp();

    float o[8][4];
#pragma unroll
    for (int j = 0; j < 8; j++)
#pragma unroll
        for (int e = 0; e < 4; e++) o[j][e] = 0.0f;
    float m0 = -1e30f, m1 = -1e30f, l0 = 0.0f, l1 = 0.0f;

    for (int c = 0; c < nc; c++) {
        if (c + 1 < nc) { issue(c + 1, (c + 1) & 1); cpwait<1>(); }
        else            { cpwait<0>(); }
        __syncthreads();
        const uint32_t ksb = su32(sh + (c & 1) * FKV);
        const uint32_t vsb = su32(sh + (2 + (c & 1)) * FKV);

        const int lim = (c >= 2 * qt) ? (16 * warp + 15 - 64 * (c - 2 * qt)) : 127;
        if (lim >= 0) {
            const int j2max = min(3, lim >> 4);
            const int jmax = min(7, 2 * j2max + 1);

            // ---- S = Q K^T ----
            float s[8][4];
#pragma unroll
            for (int j = 0; j < 8; j++)
#pragma unroll
                for (int e = 0; e < 4; e++) s[j][e] = 0.0f;
#pragma unroll
            for (int kc = 0; kc < 8; kc++) {
#pragma unroll
                for (int j2 = 0; j2 < 4; j2++) {
                    if (j2 > j2max) break;
                    uint32_t b0, b1, b2, b3;
                    ldsm_x4(b0, b1, b2, b3,
                            ksb + 4 * ((16 * j2) * FLD + 8 * kc + boff));
                    mma_tf32(s[2 * j2], qa[kc][0], qa[kc][1], qa[kc][2], qa[kc][3], b0, b1);
                    mma_tf32(s[2 * j2 + 1], qa[kc][0], qa[kc][1], qa[kc][2], qa[kc][3], b2, b3);
                }
            }

            // ---- causal mask ----
            if (c >= 2 * qt) {
                const int kb = 64 * (c - 2 * qt);
                const int row0 = 16 * warp + g, row1 = row0 + 8;
#pragma unroll
                for (int j = 0; j < 8; j++) {
                    if (j > jmax) break;
                    int col = kb + 8 * j + 2 * tg;
                    if (col     > row0) s[j][0] = -1e30f;
                    if (col + 1 > row0) s[j][1] = -1e30f;
                    if (col     > row1) s[j][2] = -1e30f;
                    if (col + 1 > row1) s[j][3] = -1e30f;
                }
            }

            // ---- online softmax (rows g, g+8) ----
            float rm0 = -1e30f, rm1 = -1e30f;
#pragma unroll
            for (int j = 0; j < 8; j++) {
                if (j > jmax) break;
                rm0 = fmaxf(rm0, fmaxf(s[j][0], s[j][1]));
                rm1 = fmaxf(rm1, fmaxf(s[j][2], s[j][3]));
            }
            rm0 = fmaxf(rm0, __shfl_xor_sync(0xffffffffu, rm0, 1));
            rm0 = fmaxf(rm0, __shfl_xor_sync(0xffffffffu, rm0, 2));
            rm1 = fmaxf(rm1, __shfl_xor_sync(0xffffffffu, rm1, 1));
            rm1 = fmaxf(rm1, __shfl_xor_sync(0xffffffffu, rm1, 2));
            float mn0 = fmaxf(m0, rm0), mn1 = fmaxf(m1, rm1);
            float corr0 = ex2(m0 - mn0), corr1 = ex2(m1 - mn1);
            float rs0 = 0.0f, rs1 = 0.0f;
#pragma unroll
            for (int j = 0; j < 8; j++) {
                if (j > jmax) break;
                s[j][0] = ex2(s[j][0] - mn0); rs0 += s[j][0];
                s[j][1] = ex2(s[j][1] - mn0); rs0 += s[j][1];
                s[j][2] = ex2(s[j][2] - mn1); rs1 += s[j][2];
                s[j][3] = ex2(s[j][3] - mn1); rs1 += s[j][3];
            }
            rs0 += __shfl_xor_sync(0xffffffffu, rs0, 1);
            rs0 += __shfl_xor_sync(0xffffffffu, rs0, 2);
            rs1 += __shfl_xor_sync(0xffffffffu, rs1, 1);
            rs1 += __shfl_xor_sync(0xffffffffu, rs1, 2);
            l0 = l0 * corr0 + rs0; m0 = mn0;
            l1 = l1 * corr1 + rs1; m1 = mn1;
#pragma unroll
            for (int j = 0; j < 8; j++) {
                o[j][0] *= corr0; o[j][1] *= corr0;
                o[j][2] *= corr1; o[j][3] *= corr1;
            }

            // ---- P to warp-private band (tf32) ----
            const int pr0 = (16 * warp + g) * FLD, pr1 = (16 * warp + g + 8) * FLD;
#pragma unroll
            for (int j = 0; j < 8; j++) {
                if (j > jmax) break;
                *(float2*)&Ss[pr0 + 8 * j + 2 * tg] =
                    make_float2(ftf(s[j][0]), ftf(s[j][1]));
                *(float2*)&Ss[pr1 + 8 * j + 2 * tg] =
                    make_float2(ftf(s[j][2]), ftf(s[j][3]));
            }
            __syncwarp();

            // ---- O += P @ V  (V^T tiles, B-frags via ldmatrix) ----
#pragma unroll
            for (int kc = 0; kc < 8; kc++) {
                if (kc > jmax) break;
                uint32_t pa0, pa1, pa2, pa3;
                ldsm_x4(pa0, pa1, pa2, pa3,
                        ssb + 4 * ((16 * warp) * FLD + 8 * kc + aoff));
#pragma unroll
                for (int j2 = 0; j2 < 4; j2++) {
                    uint32_t b0, b1, b2, b3;
                    ldsm_x4(b0, b1, b2, b3,
                            vsb + 4 * ((16 * j2) * FLD + 8 * kc + boff));
                    mma_tf32(o[2 * j2], pa0, pa1, pa2, pa3, b0, b1);
                    mma_tf32(o[2 * j2 + 1], pa0, pa1, pa2, pa3, b2, b3);
                }
            }
            __syncwarp();
        }
        __syncthreads();
    }

    // ---- write O (tf32-rounded, feeds proj cp.async) in [B,T,NH,HS] ----
    const float inv0 = 1.0f / l0, inv1 = 1.0f / l1;
    const int b_ = hb >> 4, head = hb & 15;
    const int t0 = qt * 128 + 16 * warp + g, t1 = t0 + 8;
    float* y0 = g_y + (((size_t)(b_ * TT + t0)) * NH_ + head) * HS_;
    float* y1 = g_y + (((size_t)(b_ * TT + t1)) * NH_ + head) * HS_;
#pragma unroll
    for (int j = 0; j < 8; j++) {
        *(float2*)&y0[8 * j + 2 * tg] =
            make_float2(ftf(o[j][0] * inv0), ftf(o[j][1] * inv0));
        *(float2*)&y1[8 * j + 2 * tg] =
            make_float2(ftf(o[j][2] * inv1), ftf(o[j][3] * inv1));
    }
}

// ---------------------------------------------------------------------------
extern "C" void kernel_launch(void* const* d_in, const int* in_sizes, int n_in,
                              void* d_out, int out_size)
{
    const float* x      = (const float*)d_in[0];  // [B,T,C]
    const float* W_attn = (const float*)d_in[1];  // [3C,C]
    const float* W_proj = (const float*)d_in[2];  // [C,C]
    // d_in[3..6] feed a discarded branch — skipped.
    float* out = (float*)d_out;                   // [B,T,C] fp32

    cudaFuncSetAttribute(gemm_tf32_kernel<0>,
                         cudaFuncAttributeMaxDynamicSharedMemorySize, GEMM_SMEM);
    cudaFuncSetAttribute(gemm_tf32_kernel<1>,
                         cudaFuncAttributeMaxDynamicSharedMemorySize, GEMM_SMEM);
    cudaFuncSetAttribute(flash_mma_kernel,
                         cudaFuncAttributeMaxDynamicSharedMemorySize, FLASH_SMEM);

    float* xr;  cudaGetSymbolAddress((void**)&xr,  g_xr);
    float* wr;  cudaGetSymbolAddress((void**)&wr,  g_wr);
    float* wpr; cudaGetSymbolAddress((void**)&wpr, g_wpr);

    const int n4x = BB * TT * CC / 4;
    const int n4w = 3 * CC * CC / 4;
    const int n4p = CC * CC / 4;
    tf32_round_kernel<<<(n4x + 255) / 256, 256>>>(x, xr, n4x);
    tf32_round_kernel<<<(n4w + 255) / 256, 256>>>(W_attn, wr, n4w);
    tf32_round_kernel<<<(n4p + 255) / 256, 256>>>(W_proj, wpr, n4p);

    gemm_tf32_kernel<0><<<dim3(3 * CC / 128, BB * TT / 128), 256, GEMM_SMEM>>>(xr, wr, nullptr);
    flash_mma_kernel<<<dim3(TT / 128, HB_), 256, FLASH_SMEM>>>();
    gemm_tf32_kernel<1><<<dim3(CC / 128, BB * TT / 128), 256, GEMM_SMEM>>>(xr, wpr, out);
}

// round 10
// speedup vs baseline: 2.1160x; 1.0020x over previous
#include <cuda_runtime.h>
#include <mma.h>
#include <cstdint>
using namespace nvcuda;

#define BB  4
#define TT  2048
#define CC  1024
#define NH_ 16
#define HS_ 64
#define HB_ (BB * NH_)   // 64 (b,h) pairs

// Scratch (device globals — no allocation allowed)
__device__ float g_q[(size_t)BB * NH_ * TT * HS_];   // [B,NH,t,d], tf32
__device__ float g_k[(size_t)BB * NH_ * TT * HS_];   // [B,NH,t,d], tf32
__device__ float g_v[(size_t)BB * NH_ * TT * HS_];   // [B,NH,d,t] TRANSPOSED, tf32
__device__ float g_y[(size_t)BB * TT * CC];          // [B,T,NH,HS], tf32
__device__ float g_xr[(size_t)BB * TT * CC];         // tf32-rounded x
__device__ float g_wr[(size_t)3 * CC * CC];          // tf32-rounded W_attn
__device__ float g_wpr[(size_t)CC * CC];             // tf32-rounded W_proj

__device__ __forceinline__ float ftf(float x) { return wmma::__float_to_tf32(x); }
__device__ __forceinline__ float ex2(float x) {
    float r; asm("ex2.approx.ftz.f32 %0, %1;" : "=f"(r) : "f"(x)); return r;
}
__device__ __forceinline__ unsigned su32(const void* p) {
    return (unsigned)__cvta_generic_to_shared(p);
}
#define CPA16(dst, src) \
    asm volatile("cp.async.cg.shared.global [%0], [%1], 16;" :: "r"(dst), "l"(src))
#define CPCOMMIT() asm volatile("cp.async.commit_group;")
template<int N> __device__ __forceinline__ void cpwait() {
    asm volatile("cp.async.wait_group %0;" :: "n"(N));
}

// Raw tf32 MMA m16n8k8 (lane l: g=l>>2, tg=l&3):
//   A: a0=(g,tg) a1=(g+8,tg) a2=(g,tg+4) a3=(g+8,tg+4)
//   B: b0=(k=tg,n=g) b1=(k=tg+4,n=g)
//   C: c0=(g,2tg) c1=(g,2tg+1) c2=(g+8,2tg) c3=(g+8,2tg+1)
__device__ __forceinline__ void mma_tf32(float* d,
    uint32_t a0, uint32_t a1, uint32_t a2, uint32_t a3,
    uint32_t b0, uint32_t b1)
{
    asm volatile("mma.sync.aligned.m16n8k8.row.col.f32.tf32.tf32.f32 "
        "{%0,%1,%2,%3}, {%4,%5,%6,%7}, {%8,%9}, {%0,%1,%2,%3};"
        : "+f"(d[0]), "+f"(d[1]), "+f"(d[2]), "+f"(d[3])
        : "r"(a0), "r"(a1), "r"(a2), "r"(a3), "r"(b0), "r"(b1));
}

__device__ __forceinline__ void ldsm_x4(uint32_t& r0, uint32_t& r1,
                                        uint32_t& r2, uint32_t& r3, uint32_t addr)
{
    asm volatile("ldmatrix.sync.aligned.m8n8.x4.shared.b16 {%0,%1,%2,%3}, [%4];"
        : "=r"(r0), "=r"(r1), "=r"(r2), "=r"(r3) : "r"(addr));
}

// Per-lane ldmatrix row-address offsets (floats, relative to tile origin).
#define AOFF(S) ((((lane & 7) + ((lane >> 3) & 1) * 8) * (S)) + ((lane >> 4) & 1) * 4)
#define BOFF(S) ((((lane & 7) + ((lane >> 4) & 1) * 8) * (S)) + ((lane >> 3) & 1) * 4)

// ---------------------------------------------------------------------------
// tf32 RN pre-round pass
// ---------------------------------------------------------------------------
__global__ void tf32_round_kernel(const float* __restrict__ src,
                                  float* __restrict__ dst, int n4)
{
    int i = blockIdx.x * blockDim.x + threadIdx.x;
    if (i < n4) {
        float4 v = ((const float4*)src)[i];
        v.x = ftf(v.x); v.y = ftf(v.y); v.z = ftf(v.z); v.w = ftf(v.w);
        ((float4*)dst)[i] = v;
    }
}

// ---------------------------------------------------------------------------
// TF32 GEMM: 3-stage cp.async ring, ONE barrier per K-iter, fill-after-barrier.
// Block 128x128, BK=32, 256 threads = 8 warps (2m x 4n), warp tile 64x32.
// EPI==0: scatter q/k ([B,NH,t,d]) and v TRANSPOSED ([B,NH,d,t]), ftf-rounded.
// EPI==1: A := g_y, plain fp32 store.
// ---------------------------------------------------------------------------
#define GLD 36
#define GT (128 * GLD)
#define GSTAGE (2 * GT)                 // A+B floats per stage
#define GEMM_SMEM (3 * GSTAGE * 4)      // 110592 B

template<int EPI>
__global__ __launch_bounds__(256, 2) void gemm_tf32_kernel(
    const float* __restrict__ A, const float* __restrict__ W,
    float* __restrict__ out)
{
    extern __shared__ __align__(16) float sh[];   // 3 x [A|B]

    const int tid = threadIdx.x;
    const int bn = blockIdx.x, bm = blockIdx.y;
    const int warp = tid >> 5;
    const int lane = tid & 31;
    const int g = lane >> 2, tg = lane & 3;
    const int wm = warp >> 2, wn = warp & 3;
    const int lrow = tid >> 1, lcol = (tid & 1) * 16;

    const int aoff = AOFF(GLD);
    const int boff = BOFF(GLD);

    float c[4][4][4];
#pragma unroll
    for (int i = 0; i < 4; i++)
#pragma unroll
        for (int j = 0; j < 4; j++)
#pragma unroll
            for (int e = 0; e < 4; e++) c[i][j][e] = 0.0f;

    const float* Asrc = (EPI == 1) ? (const float*)g_y : A;
    const float* Ag = Asrc + (size_t)(bm * 128 + lrow) * CC + lcol;
    const float* Wg = W + (size_t)(bn * 128 + lrow) * CC + lcol;
    const uint32_t shb = su32(sh);

    auto fill = [&](int it) {
        int s = it % 3;
        uint32_t da = shb + 4 * (s * GSTAGE + lrow * GLD + lcol);
        uint32_t db = da + 4 * GT;
        const float* ga = Ag + it * 32;
        const float* gb = Wg + it * 32;
#pragma unroll
        for (int u = 0; u < 4; u++) {
            CPA16(da + u * 16, ga + u * 4);
            CPA16(db + u * 16, gb + u * 4);
        }
        CPCOMMIT();
    };

    fill(0); fill(1);
    const int NIT = CC / 32;
    for (int it = 0; it < NIT; it++) {
        if (it + 1 < NIT) cpwait<1>();   // fill(it) done; fill(it+1) may stream
        else              cpwait<0>();
        __syncthreads();                 // single barrier: publishes stage it,
                                         // proves compute(it-1) done block-wide
        if (it + 2 < NIT) fill(it + 2);  // overwrites stage last read at it-1

        const uint32_t asb = shb + 4 * ((it % 3) * GSTAGE);
        const uint32_t bsb = asb + 4 * GT;
#pragma unroll
        for (int ks = 0; ks < 4; ks++) {
            uint32_t af[4][4], bf[2][4];
#pragma unroll
            for (int i = 0; i < 4; i++)
                ldsm_x4(af[i][0], af[i][1], af[i][2], af[i][3],
                        asb + 4 * ((wm * 64 + i * 16) * GLD + ks * 8 + aoff));
#pragma unroll
            for (int j2 = 0; j2 < 2; j2++)
                ldsm_x4(bf[j2][0], bf[j2][1], bf[j2][2], bf[j2][3],
                        bsb + 4 * ((wn * 32 + j2 * 16) * GLD + ks * 8 + boff));
#pragma unroll
            for (int i = 0; i < 4; i++)
#pragma unroll
                for (int j = 0; j < 4; j++)
                    mma_tf32(c[i][j], af[i][0], af[i][1], af[i][2], af[i][3],
                             bf[j >> 1][(j & 1) * 2], bf[j >> 1][(j & 1) * 2 + 1]);
        }
    }

#pragma unroll
    for (int i = 0; i < 4; i++) {
        int mA = bm * 128 + wm * 64 + i * 16 + g;
        int mB = mA + 8;
#pragma unroll
        for (int j = 0; j < 4; j++) {
            int n = bn * 128 + wn * 32 + j * 8 + 2 * tg;
            if (EPI == 0) {
                int which = n >> 10;
                int cc = n & 1023;
                int head = cc >> 6, d = cc & 63;
                int bA = mA >> 11, tA = mA & 2047;
                int bB = mB >> 11, tB = mB & 2047;
                if (which == 2) {   // v: transposed [B,NH,d,t]
                    float* base = g_v + ((size_t)(bA * NH_ + head) * HS_) * TT;
                    base[(size_t)(d    ) * TT + tA] = ftf(c[i][j][0]);
                    base[(size_t)(d + 1) * TT + tA] = ftf(c[i][j][1]);
                    float* baseB = g_v + ((size_t)(bB * NH_ + head) * HS_) * TT;
                    baseB[(size_t)(d    ) * TT + tB] = ftf(c[i][j][2]);
                    baseB[(size_t)(d + 1) * TT + tB] = ftf(c[i][j][3]);
                } else {
                    float* dst = (which == 0) ? g_q : g_k;
                    *(float2*)&dst[(((size_t)(bA * NH_ + head)) * TT + tA) * HS_ + d] =
                        make_float2(ftf(c[i][j][0]), ftf(c[i][j][1]));
                    *(float2*)&dst[(((size_t)(bB * NH_ + head)) * TT + tB) * HS_ + d] =
                        make_float2(ftf(c[i][j][2]), ftf(c[i][j][3]));
                }
            } else {
                *(float2*)&out[(size_t)mA * CC + n] = make_float2(c[i][j][0], c[i][j][1]);
                *(float2*)&out[(size_t)mB * CC + n] = make_float2(c[i][j][2], c[i][j][3]);
            }
        }
    }
}

// ---------------------------------------------------------------------------
// Flash attention: register-resident mma.sync + ldmatrix, ONE barrier per
// chunk (issue(c+1) moved after the barrier; it writes the buffer compute(c-1)
// used, which the barrier proves is drained).
// ---------------------------------------------------------------------------
#define FLD 68
#define FKV (64 * FLD)
#define FSS (128 * FLD)
#define FLASH_SMEM ((4 * FKV + FSS) * 4)

__global__ __launch_bounds__(256) void flash_mma_kernel()
{
    extern __shared__ __align__(16) float sh[];
    float* Ss = sh + 4 * FKV;

    const int qt = gridDim.x - 1 - blockIdx.x;   // heavy tiles first
    const int hb = blockIdx.y;
    const int tid = threadIdx.x;
    const int warp = tid >> 5;
    const int lane = tid & 31;
    const int g = lane >> 2, tg = lane & 3;
    const int lr = tid >> 2, lq = (tid & 3) * 16;
    const int rq = tid >> 1, hq = tid & 1;

    const int aoff = AOFF(FLD);
    const int boff = BOFF(FLD);
    const int nc = 2 * qt + 2;

    auto issue = [&](int c, int s) {
        const float* kp = g_k + ((size_t)hb * TT + c * 64 + lr) * HS_ + lq;
        const float* vp = g_v + ((size_t)hb * HS_ + lr) * TT + c * 64 + lq;  // [d][t]
        unsigned dk = su32(sh + s * FKV + lr * FLD + lq);
        unsigned dv = su32(sh + (2 + s) * FKV + lr * FLD + lq);
#pragma unroll
        for (int u = 0; u < 4; u++) {
            CPA16(dk + u * 16, kp + u * 4);
            CPA16(dv + u * 16, vp + u * 4);
        }
        CPCOMMIT();
    };

    issue(0, 0);

    // ---- stage Q through own Ss band, pull A-frags via ldmatrix ----
    const float* qp = g_q + ((size_t)hb * TT + qt * 128) * HS_;
    const float qs = 0.125f * 1.44269504f;
#pragma unroll
    for (int u = 0; u < 8; u++) {
        float4 v = *(const float4*)(qp + rq * 64 + hq * 32 + u * 4);
        v.x = ftf(v.x * qs); v.y = ftf(v.y * qs);
        v.z = ftf(v.z * qs); v.w = ftf(v.w * qs);
        *(float4*)&Ss[rq * FLD + hq * 32 + u * 4] = v;
    }
    __syncwarp();
    const uint32_t ssb = su32(Ss);
    uint32_t qa[8][4];
#pragma unroll
    for (int kc = 0; kc < 8; kc++)
        ldsm_x4(qa[kc][0], qa[kc][1], qa[kc][2], qa[kc][3],
                ssb + 4 * ((16 * warp) * FLD + 8 * kc + aoff));
    __syncwarp();

    float o[8][4];
#pragma unroll
    for (int j = 0; j < 8; j++)
#pragma unroll
        for (int e = 0; e < 4; e++) o[j][e] = 0.0f;
    float m0 = -1e30f, m1 = -1e30f, l0 = 0.0f, l1 = 0.0f;

    for (int c = 0; c < nc; c++) {
        cpwait<0>();            // own fills for chunk c complete
        __syncthreads();        // publish buffer c; proves compute(c-1) drained
        if (c + 1 < nc) issue(c + 1, (c + 1) & 1);   // overlaps compute(c)

        const uint32_t ksb = su32(sh + (c & 1) * FKV);
        const uint32_t vsb = su32(sh + (2 + (c & 1)) * FKV);

        const int lim = (c >= 2 * qt) ? (16 * warp + 15 - 64 * (c - 2 * qt)) : 127;
        if (lim >= 0) {
            const int j2max = min(3, lim >> 4);
            const int jmax = min(7, 2 * j2max + 1);

            // ---- S = Q K^T ----
            float s[8][4];
#pragma unroll
            for (int j = 0; j < 8; j++)
#pragma unroll
                for (int e = 0; e < 4; e++) s[j][e] = 0.0f;
#pragma unroll
            for (int kc = 0; kc < 8; kc++) {
#pragma unroll
                for (int j2 = 0; j2 < 4; j2++) {
                    if (j2 > j2max) break;
                    uint32_t b0, b1, b2, b3;
                    ldsm_x4(b0, b1, b2, b3,
                            ksb + 4 * ((16 * j2) * FLD + 8 * kc + boff));
                    mma_tf32(s[2 * j2], qa[kc][0], qa[kc][1], qa[kc][2], qa[kc][3], b0, b1);
                    mma_tf32(s[2 * j2 + 1], qa[kc][0], qa[kc][1], qa[kc][2], qa[kc][3], b2, b3);
                }
            }

            // ---- causal mask ----
            if (c >= 2 * qt) {
                const int kb = 64 * (c - 2 * qt);
                const int row0 = 16 * warp + g, row1 = row0 + 8;
#pragma unroll
                for (int j = 0; j < 8; j++) {
                    if (j > jmax) break;
                    int col = kb + 8 * j + 2 * tg;
                    if (col     > row0) s[j][0] = -1e30f;
                    if (col + 1 > row0) s[j][1] = -1e30f;
                    if (col     > row1) s[j][2] = -1e30f;
                    if (col + 1 > row1) s[j][3] = -1e30f;
                }
            }

            // ---- online softmax (rows g, g+8) ----
            float rm0 = -1e30f, rm1 = -1e30f;
#pragma unroll
            for (int j = 0; j < 8; j++) {
                if (j > jmax) break;
                rm0 = fmaxf(rm0, fmaxf(s[j][0], s[j][1]));
                rm1 = fmaxf(rm1, fmaxf(s[j][2], s[j][3]));
            }
            rm0 = fmaxf(rm0, __shfl_xor_sync(0xffffffffu, rm0, 1));
            rm0 = fmaxf(rm0, __shfl_xor_sync(0xffffffffu, rm0, 2));
            rm1 = fmaxf(rm1, __shfl_xor_sync(0xffffffffu, rm1, 1));
            rm1 = fmaxf(rm1, __shfl_xor_sync(0xffffffffu, rm1, 2));
            float mn0 = fmaxf(m0, rm0), mn1 = fmaxf(m1, rm1);
            float corr0 = ex2(m0 - mn0), corr1 = ex2(m1 - mn1);
            float rs0 = 0.0f, rs1 = 0.0f;
#pragma unroll
            for (int j = 0; j < 8; j++) {
                if (j > jmax) break;
                s[j][0] = ex2(s[j][0] - mn0); rs0 += s[j][0];
                s[j][1] = ex2(s[j][1] - mn0); rs0 += s[j][1];
                s[j][2] = ex2(s[j][2] - mn1); rs1 += s[j][2];
                s[j][3] = ex2(s[j][3] - mn1); rs1 += s[j][3];
            }
            rs0 += __shfl_xor_sync(0xffffffffu, rs0, 1);
            rs0 += __shfl_xor_sync(0xffffffffu, rs0, 2);
            rs1 += __shfl_xor_sync(0xffffffffu, rs1, 1);
            rs1 += __shfl_xor_sync(0xffffffffu, rs1, 2);
            l0 = l0 * corr0 + rs0; m0 = mn0;
            l1 = l1 * corr1 + rs1; m1 = mn1;
#pragma unroll
            for (int j = 0; j < 8; j++) {
                o[j][0] *= corr0; o[j][1] *= corr0;
                o[j][2] *= corr1; o[j][3] *= corr1;
            }

            // ---- P to warp-private band (tf32) ----
            const int pr0 = (16 * warp + g) * FLD, pr1 = (16 * warp + g + 8) * FLD;
#pragma unroll
            for (int j = 0; j < 8; j++) {
                if (j > jmax) break;
                *(float2*)&Ss[pr0 + 8 * j + 2 * tg] =
                    make_float2(ftf(s[j][0]), ftf(s[j][1]));
                *(float2*)&Ss[pr1 + 8 * j + 2 * tg] =
                    make_float2(ftf(s[j][2]), ftf(s[j][3]));
            }
            __syncwarp();

            // ---- O += P @ V  (V^T tiles, B-frags via ldmatrix) ----
#pragma unroll
            for (int kc = 0; kc < 8; kc++) {
                if (kc > jmax) break;
                uint32_t pa0, pa1, pa2, pa3;
                ldsm_x4(pa0, pa1, pa2, pa3,
                        ssb + 4 * ((16 * warp) * FLD + 8 * kc + aoff));
#pragma unroll
                for (int j2 = 0; j2 < 4; j2++) {
                    uint32_t b0, b1, b2, b3;
                    ldsm_x4(b0, b1, b2, b3,
                            vsb + 4 * ((16 * j2) * FLD + 8 * kc + boff));
                    mma_tf32(o[2 * j2], pa0, pa1, pa2, pa3, b0, b1);
                    mma_tf32(o[2 * j2 + 1], pa0, pa1, pa2, pa3, b2, b3);
                }
            }
            __syncwarp();
        }
    }

    // ---- write O (tf32-rounded, feeds proj cp.async) in [B,T,NH,HS] ----
    const float inv0 = 1.0f / l0, inv1 = 1.0f / l1;
    const int b_ = hb >> 4, head = hb & 15;
    const int t0 = qt * 128 + 16 * warp + g, t1 = t0 + 8;
    float* y0 = g_y + (((size_t)(b_ * TT + t0)) * NH_ + head) * HS_;
    float* y1 = g_y + (((size_t)(b_ * TT + t1)) * NH_ + head) * HS_;
#pragma unroll
    for (int j = 0; j < 8; j++) {
        *(float2*)&y0[8 * j + 2 * tg] =
            make_float2(ftf(o[j][0] * inv0), ftf(o[j][1] * inv0));
        *(float2*)&y1[8 * j + 2 * tg] =
            make_float2(ftf(o[j][2] * inv1), ftf(o[j][3] * inv1));
    }
}

// ---------------------------------------------------------------------------
extern "C" void kernel_launch(void* const* d_in, const int* in_sizes, int n_in,
                              void* d_out, int out_size)
{
    const float* x      = (const float*)d_in[0];  // [B,T,C]
    const float* W_attn = (const float*)d_in[1];  // [3C,C]
    const float* W_proj = (const float*)d_in[2];  // [C,C]
    // d_in[3..6] feed a discarded branch — skipped.
    float* out = (float*)d_out;                   // [B,T,C] fp32

    cudaFuncSetAttribute(gemm_tf32_kernel<0>,
                         cudaFuncAttributeMaxDynamicSharedMemorySize, GEMM_SMEM);
    cudaFuncSetAttribute(gemm_tf32_kernel<1>,
                         cudaFuncAttributeMaxDynamicSharedMemorySize, GEMM_SMEM);
    cudaFuncSetAttribute(flash_mma_kernel,
                         cudaFuncAttributeMaxDynamicSharedMemorySize, FLASH_SMEM);

    float* xr;  cudaGetSymbolAddress((void**)&xr,  g_xr);
    float* wr;  cudaGetSymbolAddress((void**)&wr,  g_wr);
    float* wpr; cudaGetSymbolAddress((void**)&wpr, g_wpr);

    const int n4x = BB * TT * CC / 4;
    const int n4w = 3 * CC * CC / 4;
    const int n4p = CC * CC / 4;
    tf32_round_kernel<<<(n4x + 255) / 256, 256>>>(x, xr, n4x);
    tf32_round_kernel<<<(n4w + 255) / 256, 256>>>(W_attn, wr, n4w);
    tf32_round_kernel<<<(n4p + 255) / 256, 256>>>(W_proj, wpr, n4p);

    gemm_tf32_kernel<0><<<dim3(3 * CC / 128, BB * TT / 128), 256, GEMM_SMEM>>>(xr, wr, nullptr);
    flash_mma_kernel<<<dim3(TT / 128, HB_), 256, FLASH_SMEM>>>();
    gemm_tf32_kernel<1><<<dim3(CC / 128, BB * TT / 128), 256, GEMM_SMEM>>>(xr, wpr, out);
}